// round 9
// baseline (speedup 1.0000x reference)
#include <cuda_runtime.h>

#define FULL 0xFFFFFFFFu
#define NQ 9
#define NL 2

// Precomputed Rot matrices: [layer][qubit][u00r,u00i,u01r,u01i,u10r,u10i,u11r,u11i]
__device__ float g_rot[NL * NQ * 8];

__global__ void rot_precompute(const float* __restrict__ w) {
    int i = threadIdx.x;
    if (i >= NL * NQ) return;
    float phi = w[i * 3 + 0], theta = w[i * 3 + 1], omega = w[i * 3 + 2];
    float st, ct; sincosf(0.5f * theta, &st, &ct);
    float sp, cp; sincosf(0.5f * (phi + omega), &sp, &cp);
    float sm, cm; sincosf(0.5f * (phi - omega), &sm, &cm);
    // u00 = e^{-i(phi+omega)/2} * cos(theta/2)
    g_rot[i * 8 + 0] = cp * ct;  g_rot[i * 8 + 1] = -sp * ct;
    // u01 = -e^{+i(phi-omega)/2} * sin(theta/2)
    g_rot[i * 8 + 2] = -cm * st; g_rot[i * 8 + 3] = -sm * st;
    // u10 = e^{-i(phi-omega)/2} * sin(theta/2)
    g_rot[i * 8 + 4] = cm * st;  g_rot[i * 8 + 5] = -sm * st;
    // u11 = e^{+i(phi+omega)/2} * cos(theta/2)
    g_rot[i * 8 + 6] = cp * ct;  g_rot[i * 8 + 7] = sp * ct;
}

// Generic 1-qubit gate on qubit Q. Qubits 0..3 live in the per-lane index
// bits (local), qubits 4..8 live in the lane-id bits (cross-lane shuffles).
template <int Q>
__device__ __forceinline__ void gate1(float* sr, float* si,
                                      float u00r, float u00i, float u01r, float u01i,
                                      float u10r, float u10i, float u11r, float u11i,
                                      int lane) {
    if (Q < 4) {
#pragma unroll
        for (int t = 0; t < 8; t++) {
            const int j0 = ((t >> Q) << (Q + 1)) | (t & ((1 << Q) - 1));
            const int j1 = j0 | (1 << Q);
            float ar = sr[j0], ai = si[j0], br = sr[j1], bi = si[j1];
            sr[j0] = u00r * ar - u00i * ai + u01r * br - u01i * bi;
            si[j0] = u00r * ai + u00i * ar + u01r * bi + u01i * br;
            sr[j1] = u10r * ar - u10i * ai + u11r * br - u11i * bi;
            si[j1] = u10r * ai + u10i * ar + u11r * bi + u11i * br;
        }
    } else {
        const int m = 1 << (Q - 4);
        const bool hi = (lane & m) != 0;
        // out = va*mine + vb*partner  (va = hi? u11:u00, vb = hi? u10:u01)
        const float var = hi ? u11r : u00r, vai = hi ? u11i : u00i;
        const float vbr = hi ? u10r : u01r, vbi = hi ? u10i : u01i;
#pragma unroll
        for (int j = 0; j < 16; j++) {
            float pr = __shfl_xor_sync(FULL, sr[j], m);
            float pi = __shfl_xor_sync(FULL, si[j], m);
            float mr = sr[j], mi = si[j];
            sr[j] = var * mr - vai * mi + vbr * pr - vbi * pi;
            si[j] = var * mi + vai * mr + vbr * pi + vbi * pr;
        }
    }
}

// RX gate: u = [[c, -i s], [-i s, c]] — symmetric, so cross-lane form is uniform.
template <int Q>
__device__ __forceinline__ void gate_rx(float* sr, float* si, float c, float s) {
    if (Q < 4) {
#pragma unroll
        for (int t = 0; t < 8; t++) {
            const int j0 = ((t >> Q) << (Q + 1)) | (t & ((1 << Q) - 1));
            const int j1 = j0 | (1 << Q);
            float ar = sr[j0], ai = si[j0], br = sr[j1], bi = si[j1];
            sr[j0] = c * ar + s * bi;
            si[j0] = c * ai - s * br;
            sr[j1] = c * br + s * ai;
            si[j1] = c * bi - s * ar;
        }
    } else {
        const int m = 1 << (Q - 4);
#pragma unroll
        for (int j = 0; j < 16; j++) {
            float pr = __shfl_xor_sync(FULL, sr[j], m);
            float pi = __shfl_xor_sync(FULL, si[j], m);
            float mr = sr[j], mi = si[j];
            sr[j] = c * mr + s * pi;
            si[j] = c * mi - s * pr;
        }
    }
}

template <int C, int T>
__device__ __forceinline__ void cnot(float* sr, float* si, int lane) {
    if (C < 4 && T < 4) {
        // pure register permutation
#pragma unroll
        for (int t = 0; t < 4; t++) {
            int j = 0, tt = t;
#pragma unroll
            for (int b = 0; b < 4; b++) {
                if (b != C && b != T) { j |= (tt & 1) << b; tt >>= 1; }
            }
            const int j0 = j | (1 << C);
            const int j1 = j0 | (1 << T);
            float tr = sr[j0]; sr[j0] = sr[j1]; sr[j1] = tr;
            float ti = si[j0]; si[j0] = si[j1]; si[j1] = ti;
        }
    } else if (C < 4 && T >= 4) {
        const int m = 1 << (T - 4);
#pragma unroll
        for (int j = 0; j < 16; j++) {
            if (j & (1 << C)) {  // compile-time condition: all lanes agree
                sr[j] = __shfl_xor_sync(FULL, sr[j], m);
                si[j] = __shfl_xor_sync(FULL, si[j], m);
            }
        }
    } else if (C >= 4 && T < 4) {
        const bool cond = (lane >> (C - 4)) & 1;
#pragma unroll
        for (int j = 0; j < 16; j++) {
            if (!(j & (1 << T))) {
                const int j1 = j | (1 << T);
                float a = sr[j], b = sr[j1];
                sr[j]  = cond ? b : a;
                sr[j1] = cond ? a : b;
                a = si[j]; b = si[j1];
                si[j]  = cond ? b : a;
                si[j1] = cond ? a : b;
            }
        }
    } else {
        const int m = 1 << (T - 4);
        const bool cond = (lane >> (C - 4)) & 1;
#pragma unroll
        for (int j = 0; j < 16; j++) {
            float pr = __shfl_xor_sync(FULL, sr[j], m);
            float pi = __shfl_xor_sync(FULL, si[j], m);
            sr[j] = cond ? pr : sr[j];
            si[j] = cond ? pi : si[j];
        }
    }
}

__global__ void __launch_bounds__(256) qk_main(const float* __restrict__ x,
                                               float* __restrict__ out, int n_patch) {
    const int warp = (blockIdx.x * blockDim.x + threadIdx.x) >> 5;
    const int lane = threadIdx.x & 31;
    if (warp >= n_patch) return;

    // patch -> (b, h, w), H = W = 64
    const int b = warp >> 12;
    const int h = (warp >> 6) & 63;
    const int w = warp & 63;

    // lanes 0..8 each load one embedding angle (3x3 neighborhood, zero padded)
    float ang = 0.0f;
    if (lane < 9) {
        const int kh = lane / 3, kw = lane % 3;
        const int hh = h - 1 + kh, ww = w - 1 + kw;
        if (hh >= 0 && hh < 64 && ww >= 0 && ww < 64)
            ang = x[(b << 12) + (hh << 6) + ww];
    }

    // state |0...0>: amplitude index = (lane << 4) | j ; qubit q <-> bit q
    float sr[16], si[16];
#pragma unroll
    for (int j = 0; j < 16; j++) { sr[j] = 0.0f; si[j] = 0.0f; }
    if (lane == 0) sr[0] = 1.0f;

    // ---- AngleEmbedding: RX(angle_q) on each qubit ----
#define APPLY_RX(Q)                                                   \
    {                                                                 \
        float a = __shfl_sync(FULL, ang, Q);                          \
        float s_, c_;                                                 \
        __sincosf(0.5f * a, &s_, &c_);                                \
        gate_rx<Q>(sr, si, c_, s_);                                   \
    }
    APPLY_RX(0) APPLY_RX(1) APPLY_RX(2) APPLY_RX(3) APPLY_RX(4)
    APPLY_RX(5) APPLY_RX(6) APPLY_RX(7) APPLY_RX(8)
#undef APPLY_RX

#define APPLY_ROT(L, Q)                                               \
    {                                                                 \
        const float* u = &g_rot[((L) * NQ + (Q)) * 8];                \
        gate1<Q>(sr, si, u[0], u[1], u[2], u[3],                      \
                 u[4], u[5], u[6], u[7], lane);                       \
    }

    // ---- Layer 0: Rot on each qubit, then CNOT ring r=1 ----
    APPLY_ROT(0, 0) APPLY_ROT(0, 1) APPLY_ROT(0, 2) APPLY_ROT(0, 3)
    APPLY_ROT(0, 4) APPLY_ROT(0, 5) APPLY_ROT(0, 6) APPLY_ROT(0, 7)
    APPLY_ROT(0, 8)
    cnot<0, 1>(sr, si, lane); cnot<1, 2>(sr, si, lane); cnot<2, 3>(sr, si, lane);
    cnot<3, 4>(sr, si, lane); cnot<4, 5>(sr, si, lane); cnot<5, 6>(sr, si, lane);
    cnot<6, 7>(sr, si, lane); cnot<7, 8>(sr, si, lane); cnot<8, 0>(sr, si, lane);

    // ---- Layer 1: Rot on each qubit, then CNOT ring r=2 ----
    APPLY_ROT(1, 0) APPLY_ROT(1, 1) APPLY_ROT(1, 2) APPLY_ROT(1, 3)
    APPLY_ROT(1, 4) APPLY_ROT(1, 5) APPLY_ROT(1, 6) APPLY_ROT(1, 7)
    APPLY_ROT(1, 8)
    cnot<0, 2>(sr, si, lane); cnot<1, 3>(sr, si, lane); cnot<2, 4>(sr, si, lane);
    cnot<3, 5>(sr, si, lane); cnot<4, 6>(sr, si, lane); cnot<5, 7>(sr, si, lane);
    cnot<6, 8>(sr, si, lane); cnot<7, 0>(sr, si, lane); cnot<8, 1>(sr, si, lane);
#undef APPLY_ROT

    // ---- <Z_0>: qubit 0 is local index bit 0 ----
    float z = 0.0f;
#pragma unroll
    for (int j = 0; j < 16; j++) {
        float p = sr[j] * sr[j] + si[j] * si[j];
        z += (j & 1) ? -p : p;
    }
#pragma unroll
    for (int o = 16; o > 0; o >>= 1) z += __shfl_xor_sync(FULL, z, o);

    if (lane == 0) out[warp] = z;
}

extern "C" void kernel_launch(void* const* d_in, const int* in_sizes, int n_in,
                              void* d_out, int out_size) {
    const float* x;
    const float* wts;
    // metadata order: x (32768 floats), weights (54 floats). Be defensive.
    if (n_in >= 2 && in_sizes[0] == NL * NQ * 3) {
        wts = (const float*)d_in[0];
        x = (const float*)d_in[1];
    } else {
        x = (const float*)d_in[0];
        wts = (const float*)d_in[1];
    }

    rot_precompute<<<1, 32>>>(wts);

    const int n_patch = out_size;          // 8*1*64*64 = 32768
    const int warps_per_block = 256 / 32;  // 8
    const int blocks = (n_patch + warps_per_block - 1) / warps_per_block;
    qk_main<<<blocks, 256>>>(x, (float*)d_out, n_patch);
}

// round 10
// speedup vs baseline: 1.1434x; 1.1434x over previous
#include <cuda_runtime.h>

#define FULL 0xFFFFFFFFu
#define NQ 9
#define NL 2

using ull = unsigned long long;

// ---------- f32x2 helpers (FFMA2 via PTX; ptxas won't auto-fuse) ----------
__device__ __forceinline__ ull fma2(ull a, ull b, ull c) {
    ull d; asm("fma.rn.f32x2 %0, %1, %2, %3;" : "=l"(d) : "l"(a), "l"(b), "l"(c)); return d;
}
__device__ __forceinline__ ull mul2(ull a, ull b) {
    ull d; asm("mul.rn.f32x2 %0, %1, %2;" : "=l"(d) : "l"(a), "l"(b)); return d;
}
__device__ __forceinline__ ull pack2(float lo, float hi) {
    ull d; asm("mov.b64 %0, {%1, %2};" : "=l"(d) : "f"(lo), "f"(hi)); return d;
}
__device__ __forceinline__ void unpack2(ull v, float& lo, float& hi) {
    asm("mov.b64 {%0, %1}, %2;" : "=f"(lo), "=f"(hi) : "l"(v));
}
__device__ __forceinline__ ull swap2(ull v) { float lo, hi; unpack2(v, lo, hi); return pack2(hi, lo); }
__device__ __forceinline__ ull splat2(float x) { return pack2(x, x); }

// ---------- precomputed Rot coefficient records: 12 ull per (layer,qubit) ----------
// q==0   : [cA_r,cB_r,cA_i,cB_i,ncA_i,ncB_i, ...]  (column-paired packs)
// 1<=q<4 : [s00r,s00i,n00i, s01r,s01i,n01i, s10r,s10i,n10i, s11r,s11i,n11i]
// q>=4   : [s00r,s11r, s00i,s11i, ns00i,ns11i, s01r,s10r, s01i,s10i, ns01i,ns10i]
__device__ ull g_rec[NL * NQ * 12];

__global__ void rot_precompute(const float* __restrict__ w) {
    int i = threadIdx.x;
    if (i >= NL * NQ) return;
    int q = i % NQ;
    float phi = w[i * 3 + 0], theta = w[i * 3 + 1], omega = w[i * 3 + 2];
    float st, ct; sincosf(0.5f * theta, &st, &ct);
    float sp, cp; sincosf(0.5f * (phi + omega), &sp, &cp);
    float sm, cm; sincosf(0.5f * (phi - omega), &sm, &cm);
    float u00r = cp * ct, u00i = -sp * ct;
    float u01r = -cm * st, u01i = -sm * st;
    float u10r = cm * st,  u10i = -sm * st;
    float u11r = cp * ct,  u11i = sp * ct;
    ull* r = &g_rec[i * 12];
    if (q == 0) {
        r[0] = pack2(u00r, u11r); r[1] = pack2(u01r, u10r);
        r[2] = pack2(u00i, u11i); r[3] = pack2(u01i, u10i);
        r[4] = pack2(-u00i, -u11i); r[5] = pack2(-u01i, -u10i);
        r[6] = r[7] = r[8] = r[9] = r[10] = r[11] = 0ull;
    } else if (q < 4) {
        r[0] = splat2(u00r); r[1] = splat2(u00i); r[2] = splat2(-u00i);
        r[3] = splat2(u01r); r[4] = splat2(u01i); r[5] = splat2(-u01i);
        r[6] = splat2(u10r); r[7] = splat2(u10i); r[8] = splat2(-u10i);
        r[9] = splat2(u11r); r[10] = splat2(u11i); r[11] = splat2(-u11i);
    } else {
        r[0] = splat2(u00r);  r[1] = splat2(u11r);
        r[2] = splat2(u00i);  r[3] = splat2(u11i);
        r[4] = splat2(-u00i); r[5] = splat2(-u11i);
        r[6] = splat2(u01r);  r[7] = splat2(u10r);
        r[8] = splat2(u01i);  r[9] = splat2(u10i);
        r[10] = splat2(-u01i); r[11] = splat2(-u10i);
    }
}

// ---------- gates on packed state: sr[8], si[8]; pack k = amps (2k, 2k+1) ----------
// amp index bit0 = lo/hi within pack; amp bits 1..3 = pack index bits 0..2;
// qubits 4..8 live on lane bits via evolving GF(2) frame (handled at call sites).

__device__ __forceinline__ void rx_q0(ull* sr, ull* si, float c, float s) {
    ull cs = splat2(c), ss = splat2(s), ns = splat2(-s);
#pragma unroll
    for (int k = 0; k < 8; k++) {
        ull swi = swap2(si[k]), swr = swap2(sr[k]);
        sr[k] = fma2(cs, sr[k], mul2(ss, swi));
        si[k] = fma2(cs, si[k], mul2(ns, swr));
    }
}

template <int P>  // qubit = P+1; pairing on pack bit P
__device__ __forceinline__ void rx_local(ull* sr, ull* si, float c, float s) {
    ull cs = splat2(c), ss = splat2(s), ns = splat2(-s);
#pragma unroll
    for (int t = 0; t < 4; t++) {
        const int k0 = ((t >> P) << (P + 1)) | (t & ((1 << P) - 1));
        const int k1 = k0 | (1 << P);
        ull ar = sr[k0], ai = si[k0], br = sr[k1], bi = si[k1];
        sr[k0] = fma2(cs, ar, mul2(ss, bi));
        si[k0] = fma2(cs, ai, mul2(ns, br));
        sr[k1] = fma2(cs, br, mul2(ss, ai));
        si[k1] = fma2(cs, bi, mul2(ns, ar));
    }
}

__device__ __forceinline__ void rx_cross(ull* sr, ull* si, float c, float s, int m) {
    ull cs = splat2(c), ss = splat2(s), ns = splat2(-s);
#pragma unroll
    for (int k = 0; k < 8; k++) {
        ull pr = __shfl_xor_sync(FULL, sr[k], m);
        ull pi = __shfl_xor_sync(FULL, si[k], m);
        sr[k] = fma2(cs, sr[k], mul2(ss, pi));
        si[k] = fma2(cs, si[k], mul2(ns, pr));
    }
}

__device__ __forceinline__ void rot_q0(ull* sr, ull* si, const ull* rec, bool swapAB) {
    ull cAr = __ldg(rec + 0), cBr = __ldg(rec + 1);
    ull cAi = __ldg(rec + 2), cBi = __ldg(rec + 3);
    ull nAi = __ldg(rec + 4), nBi = __ldg(rec + 5);
    if (swapAB) {  // folded CNOT(8,0): U <- U*X  <=>  A<->B column packs
        ull t;
        t = cAr; cAr = cBr; cBr = t;
        t = cAi; cAi = cBi; cBi = t;
        t = nAi; nAi = nBi; nBi = t;
    }
#pragma unroll
    for (int k = 0; k < 8; k++) {
        ull vr = sr[k], vi = si[k];
        ull vrs = swap2(vr), vis = swap2(vi);
        sr[k] = fma2(cAr, vr, fma2(cBr, vrs, fma2(nAi, vi, mul2(nBi, vis))));
        si[k] = fma2(cAi, vr, fma2(cBi, vrs, fma2(cAr, vi, mul2(cBr, vis))));
    }
}

template <int P>
__device__ __forceinline__ void rot_local(ull* sr, ull* si, const ull* rec) {
    ull s00r = __ldg(rec + 0), s00i = __ldg(rec + 1), n00i = __ldg(rec + 2);
    ull s01r = __ldg(rec + 3), s01i = __ldg(rec + 4), n01i = __ldg(rec + 5);
    ull s10r = __ldg(rec + 6), s10i = __ldg(rec + 7), n10i = __ldg(rec + 8);
    ull s11r = __ldg(rec + 9), s11i = __ldg(rec + 10), n11i = __ldg(rec + 11);
#pragma unroll
    for (int t = 0; t < 4; t++) {
        const int k0 = ((t >> P) << (P + 1)) | (t & ((1 << P) - 1));
        const int k1 = k0 | (1 << P);
        ull ar = sr[k0], ai = si[k0], br = sr[k1], bi = si[k1];
        sr[k0] = fma2(s00r, ar, fma2(n00i, ai, fma2(s01r, br, mul2(n01i, bi))));
        si[k0] = fma2(s00r, ai, fma2(s00i, ar, fma2(s01r, bi, mul2(s01i, br))));
        sr[k1] = fma2(s10r, ar, fma2(n10i, ai, fma2(s11r, br, mul2(n11i, bi))));
        si[k1] = fma2(s10r, ai, fma2(s10i, ar, fma2(s11r, bi, mul2(s11i, br))));
    }
}

__device__ __forceinline__ void rot_cross(ull* sr, ull* si, const ull* rec, int m, bool hi) {
    ull var_ = hi ? __ldg(rec + 1) : __ldg(rec + 0);
    ull vai_ = hi ? __ldg(rec + 3) : __ldg(rec + 2);
    ull nvai = hi ? __ldg(rec + 5) : __ldg(rec + 4);
    ull vbr_ = hi ? __ldg(rec + 7) : __ldg(rec + 6);
    ull vbi_ = hi ? __ldg(rec + 9) : __ldg(rec + 8);
    ull nvbi = hi ? __ldg(rec + 11) : __ldg(rec + 10);
#pragma unroll
    for (int k = 0; k < 8; k++) {
        ull pr = __shfl_xor_sync(FULL, sr[k], m);
        ull pi = __shfl_xor_sync(FULL, si[k], m);
        ull mr = sr[k], mi = si[k];
        sr[k] = fma2(var_, mr, fma2(nvai, mi, fma2(vbr_, pr, mul2(nvbi, pi))));
        si[k] = fma2(var_, mi, fma2(vai_, mr, fma2(vbr_, pi, mul2(vbi_, pr))));
    }
}

// exchange hi halves of two packs (CNOTs with control = amp bit0)
__device__ __forceinline__ void hi_swap(ull& a, ull& b) {
    float alo, ahi, blo, bhi;
    unpack2(a, alo, ahi); unpack2(b, blo, bhi);
    a = pack2(alo, bhi);  b = pack2(blo, ahi);
}

__global__ void __launch_bounds__(256) qk_main(const float* __restrict__ x,
                                               float* __restrict__ out, int n_patch) {
    const int warp = (blockIdx.x * blockDim.x + threadIdx.x) >> 5;
    const int lane = threadIdx.x & 31;
    if (warp >= n_patch) return;

    const int b = warp >> 12;
    const int h = (warp >> 6) & 63;
    const int w = warp & 63;

    float ang = 0.0f;
    if (lane < 9) {
        const int kh = lane / 3, kw = lane % 3;
        const int hh = h - 1 + kh, ww = w - 1 + kw;
        if (hh >= 0 && hh < 64 && ww >= 0 && ww < 64)
            ang = x[(b << 12) + (hh << 6) + ww];
    }

    // lane-bit parities (logical values of lane qubits after layer-0 frame update
    // M rows = {1,3,7,15,31}: prefix parities of physical lane bits)
    const int b0 = lane & 1, b1 = (lane >> 1) & 1, b2 = (lane >> 2) & 1;
    const int b3 = (lane >> 3) & 1, b4 = (lane >> 4) & 1;
    const int q4h = b0, q5h = q4h ^ b1, q6h = q5h ^ b2, q7h = q6h ^ b3, q8h = q7h ^ b4;

    // |0..0>
    ull sr[8], si[8];
#pragma unroll
    for (int k = 0; k < 8; k++) { sr[k] = 0ull; si[k] = 0ull; }
    sr[0] = (lane == 0) ? 0x3F800000ull : 0ull;  // lo half = 1.0f

    // ---- AngleEmbedding: RX on each qubit (frame M = I) ----
    float c_, s_, a;
    a = __shfl_sync(FULL, ang, 0); __sincosf(0.5f * a, &s_, &c_); rx_q0(sr, si, c_, s_);
    a = __shfl_sync(FULL, ang, 1); __sincosf(0.5f * a, &s_, &c_); rx_local<0>(sr, si, c_, s_);
    a = __shfl_sync(FULL, ang, 2); __sincosf(0.5f * a, &s_, &c_); rx_local<1>(sr, si, c_, s_);
    a = __shfl_sync(FULL, ang, 3); __sincosf(0.5f * a, &s_, &c_); rx_local<2>(sr, si, c_, s_);
    a = __shfl_sync(FULL, ang, 4); __sincosf(0.5f * a, &s_, &c_); rx_cross(sr, si, c_, s_, 1);
    a = __shfl_sync(FULL, ang, 5); __sincosf(0.5f * a, &s_, &c_); rx_cross(sr, si, c_, s_, 2);
    a = __shfl_sync(FULL, ang, 6); __sincosf(0.5f * a, &s_, &c_); rx_cross(sr, si, c_, s_, 4);
    a = __shfl_sync(FULL, ang, 7); __sincosf(0.5f * a, &s_, &c_); rx_cross(sr, si, c_, s_, 8);
    a = __shfl_sync(FULL, ang, 8); __sincosf(0.5f * a, &s_, &c_); rx_cross(sr, si, c_, s_, 16);

#define REC(L, Q) (&g_rec[((L) * NQ + (Q)) * 12])

    // ---- Layer 0 rots (frame M = I: masks 1,2,4,8,16; hi = lane bit) ----
    rot_q0(sr, si, REC(0, 0), false);
    rot_local<0>(sr, si, REC(0, 1));
    rot_local<1>(sr, si, REC(0, 2));
    rot_local<2>(sr, si, REC(0, 3));
    rot_cross(sr, si, REC(0, 4), 1, b0);
    rot_cross(sr, si, REC(0, 5), 2, b1);
    rot_cross(sr, si, REC(0, 6), 4, b2);
    rot_cross(sr, si, REC(0, 7), 8, b3);
    rot_cross(sr, si, REC(0, 8), 16, b4);

    // ---- Layer 0 CNOT ring r=1 ----
    // (0,1): hi-half exchange between pack pairs (k, k+1)
    hi_swap(sr[0], sr[1]); hi_swap(sr[2], sr[3]); hi_swap(sr[4], sr[5]); hi_swap(sr[6], sr[7]);
    hi_swap(si[0], si[1]); hi_swap(si[2], si[3]); hi_swap(si[4], si[5]); hi_swap(si[6], si[7]);
    // (1,2): pack swaps 1<->3, 5<->7
    { ull t; t = sr[1]; sr[1] = sr[3]; sr[3] = t; t = sr[5]; sr[5] = sr[7]; sr[7] = t;
            t = si[1]; si[1] = si[3]; si[3] = t; t = si[5]; si[5] = si[7]; si[7] = t; }
    // (2,3): pack swaps 2<->6, 3<->7
    { ull t; t = sr[2]; sr[2] = sr[6]; sr[6] = t; t = sr[3]; sr[3] = sr[7]; sr[7] = t;
            t = si[2]; si[2] = si[6]; si[6] = t; t = si[3]; si[3] = si[7]; si[7] = t; }
    // (3,4): control amp bit3 (packs 4..7), target qubit4 -> shfl mask 1 (M = I here)
#pragma unroll
    for (int k = 4; k < 8; k++) {
        sr[k] = __shfl_xor_sync(FULL, sr[k], 1);
        si[k] = __shfl_xor_sync(FULL, si[k], 1);
    }
    // (4,5),(5,6),(6,7),(7,8): absorbed into lane-frame M (rows -> {1,3,7,15,31})
    // (8,0): folded into Rot(1,0) below (control = logical q8 = parity(lane&31) = q8h)

    // ---- Layer 1 rots (frame M = {1,3,7,15,31}: masks {3,6,12,24,16}, hi = prefix parities) ----
    rot_q0(sr, si, REC(1, 0), q8h != 0);  // includes folded CNOT(8,0)
    rot_local<0>(sr, si, REC(1, 1));
    rot_local<1>(sr, si, REC(1, 2));
    rot_local<2>(sr, si, REC(1, 3));
    rot_cross(sr, si, REC(1, 4), 3, q4h);
    rot_cross(sr, si, REC(1, 5), 6, q5h);
    rot_cross(sr, si, REC(1, 6), 12, q6h);
    rot_cross(sr, si, REC(1, 7), 24, q7h);
    rot_cross(sr, si, REC(1, 8), 16, q8h);

    // ---- Layer 1 CNOT ring r=2 ----
    // (0,2): hi-half exchange pairs (k, k^2), k in {0,1,4,5}
    hi_swap(sr[0], sr[2]); hi_swap(sr[1], sr[3]); hi_swap(sr[4], sr[6]); hi_swap(sr[5], sr[7]);
    hi_swap(si[0], si[2]); hi_swap(si[1], si[3]); hi_swap(si[4], si[6]); hi_swap(si[5], si[7]);
    // (1,3): pack swaps 1<->5, 3<->7
    { ull t; t = sr[1]; sr[1] = sr[5]; sr[5] = t; t = sr[3]; sr[3] = sr[7]; sr[7] = t;
            t = si[1]; si[1] = si[5]; si[5] = t; t = si[3]; si[3] = si[7]; si[7] = t; }
    // (2,4): control amp bit2 (packs 2,3,6,7), target q4 -> mask M^-1 e0 = 3
    sr[2] = __shfl_xor_sync(FULL, sr[2], 3); si[2] = __shfl_xor_sync(FULL, si[2], 3);
    sr[3] = __shfl_xor_sync(FULL, sr[3], 3); si[3] = __shfl_xor_sync(FULL, si[3], 3);
    sr[6] = __shfl_xor_sync(FULL, sr[6], 3); si[6] = __shfl_xor_sync(FULL, si[6], 3);
    sr[7] = __shfl_xor_sync(FULL, sr[7], 3); si[7] = __shfl_xor_sync(FULL, si[7], 3);
    // (3,5): control amp bit3 (packs 4..7), target q5 -> mask M^-1 e1 = 6
#pragma unroll
    for (int k = 4; k < 8; k++) {
        sr[k] = __shfl_xor_sync(FULL, sr[k], 6);
        si[k] = __shfl_xor_sync(FULL, si[k], 6);
    }
    // (4,6),(5,7),(6,8): absorbed into frame M (rows -> {1,3,6,12,25})
    // (7,0): folded into measurement sign (cond = parity(lane & 12) = b2^b3)
    // (8,1): permutes amps within fixed bit0 -> no effect on <Z_0>, dropped

    // ---- <Z_0>: sign by amp bit0 = pack lo(+)/hi(-) ----
    float z = 0.0f;
#pragma unroll
    for (int k = 0; k < 8; k++) {
        ull pw = fma2(sr[k], sr[k], mul2(si[k], si[k]));
        float plo, phi; unpack2(pw, plo, phi);
        z += plo - phi;
    }
    if (b2 ^ b3) z = -z;  // folded CNOT(7,0)
#pragma unroll
    for (int o = 16; o > 0; o >>= 1) z += __shfl_xor_sync(FULL, z, o);

    if (lane == 0) out[warp] = z;
#undef REC
}

extern "C" void kernel_launch(void* const* d_in, const int* in_sizes, int n_in,
                              void* d_out, int out_size) {
    const float* x;
    const float* wts;
    if (n_in >= 2 && in_sizes[0] == NL * NQ * 3) {
        wts = (const float*)d_in[0];
        x = (const float*)d_in[1];
    } else {
        x = (const float*)d_in[0];
        wts = (const float*)d_in[1];
    }

    rot_precompute<<<1, 32>>>(wts);

    const int n_patch = out_size;          // 32768
    const int warps_per_block = 256 / 32;  // 8
    const int blocks = (n_patch + warps_per_block - 1) / warps_per_block;
    qk_main<<<blocks, 256>>>(x, (float*)d_out, n_patch);
}

// round 11
// speedup vs baseline: 1.3353x; 1.1678x over previous
#include <cuda_runtime.h>

#define FULL 0xFFFFFFFFu
#define NQ 9
#define NL 2

using ull = unsigned long long;

// ---------- f32x2 helpers (FFMA2 via PTX; ptxas won't auto-fuse) ----------
__device__ __forceinline__ ull fma2(ull a, ull b, ull c) {
    ull d; asm("fma.rn.f32x2 %0, %1, %2, %3;" : "=l"(d) : "l"(a), "l"(b), "l"(c)); return d;
}
__device__ __forceinline__ ull mul2(ull a, ull b) {
    ull d; asm("mul.rn.f32x2 %0, %1, %2;" : "=l"(d) : "l"(a), "l"(b)); return d;
}
__device__ __forceinline__ ull pack2(float lo, float hi) {
    ull d; asm("mov.b64 %0, {%1, %2};" : "=l"(d) : "f"(lo), "f"(hi)); return d;
}
__device__ __forceinline__ void unpack2(ull v, float& lo, float& hi) {
    asm("mov.b64 {%0, %1}, %2;" : "=f"(lo), "=f"(hi) : "l"(v));
}
__device__ __forceinline__ ull swap2(ull v) { float lo, hi; unpack2(v, lo, hi); return pack2(hi, lo); }
__device__ __forceinline__ ull splat2(float x) { return pack2(x, x); }

// ---------- precomputed Rot coefficient records: 12 ull per (layer,qubit) ----------
// Layer 0 records have diag(1,-i) folded in (phase of the RX product state),
// so the embedding can construct a purely REAL state.
// q==0   : [cA_r,cB_r,cA_i,cB_i,ncA_i,ncB_i]  (column-paired packs: A=(u00,u11), B=(u01,u10))
// 1<=q<4 : [s00r,s00i,n00i, s01r,s01i,n01i, s10r,s10i,n10i, s11r,s11i,n11i]
// q>=4   : [s00r,s11r, s00i,s11i, ns00i,ns11i, s01r,s10r, s01i,s10i, ns01i,ns10i]
__device__ ull g_rec[NL * NQ * 12];

__global__ void rot_precompute(const float* __restrict__ w) {
    int i = threadIdx.x;
    if (i >= NL * NQ) return;
    int q = i % NQ;
    float phi = w[i * 3 + 0], theta = w[i * 3 + 1], omega = w[i * 3 + 2];
    float st, ct; sincosf(0.5f * theta, &st, &ct);
    float sp, cp; sincosf(0.5f * (phi + omega), &sp, &cp);
    float sm, cm; sincosf(0.5f * (phi - omega), &sm, &cm);
    float u00r = cp * ct, u00i = -sp * ct;
    float u01r = -cm * st, u01i = -sm * st;
    float u10r = cm * st,  u10i = -sm * st;
    float u11r = cp * ct,  u11i = sp * ct;
    if (i < NQ) {
        // layer 0: fold diag(1,-i) (per-qubit phase of the RX product state)
        // column 1 of U multiplied by -i: (r + i m) * -i = m - i r
        float t;
        t = u01r; u01r = u01i; u01i = -t;
        t = u11r; u11r = u11i; u11i = -t;
    }
    ull* r = &g_rec[i * 12];
    if (q == 0) {
        r[0] = pack2(u00r, u11r); r[1] = pack2(u01r, u10r);
        r[2] = pack2(u00i, u11i); r[3] = pack2(u01i, u10i);
        r[4] = pack2(-u00i, -u11i); r[5] = pack2(-u01i, -u10i);
        r[6] = r[7] = r[8] = r[9] = r[10] = r[11] = 0ull;
    } else if (q < 4) {
        r[0] = splat2(u00r); r[1] = splat2(u00i); r[2] = splat2(-u00i);
        r[3] = splat2(u01r); r[4] = splat2(u01i); r[5] = splat2(-u01i);
        r[6] = splat2(u10r); r[7] = splat2(u10i); r[8] = splat2(-u10i);
        r[9] = splat2(u11r); r[10] = splat2(u11i); r[11] = splat2(-u11i);
    } else {
        r[0] = splat2(u00r);  r[1] = splat2(u11r);
        r[2] = splat2(u00i);  r[3] = splat2(u11i);
        r[4] = splat2(-u00i); r[5] = splat2(-u11i);
        r[6] = splat2(u01r);  r[7] = splat2(u10r);
        r[8] = splat2(u01i);  r[9] = splat2(u10i);
        r[10] = splat2(-u01i); r[11] = splat2(-u10i);
    }
}

// ---------- gates on packed state: sr[8], si[8]; pack k = amps (2k, 2k+1) ----------

__device__ __forceinline__ void rot_q0(ull* sr, ull* si, const ull* rec, bool swapAB) {
    ull cAr = __ldg(rec + 0), cBr = __ldg(rec + 1);
    ull cAi = __ldg(rec + 2), cBi = __ldg(rec + 3);
    ull nAi = __ldg(rec + 4), nBi = __ldg(rec + 5);
    if (swapAB) {  // folded CNOT(8,0): U <- U*X  <=>  A<->B column packs
        ull t;
        t = cAr; cAr = cBr; cBr = t;
        t = cAi; cAi = cBi; cBi = t;
        t = nAi; nAi = nBi; nBi = t;
    }
#pragma unroll
    for (int k = 0; k < 8; k++) {
        ull vr = sr[k], vi = si[k];
        ull vrs = swap2(vr), vis = swap2(vi);
        sr[k] = fma2(cAr, vr, fma2(cBr, vrs, fma2(nAi, vi, mul2(nBi, vis))));
        si[k] = fma2(cAi, vr, fma2(cBi, vrs, fma2(cAr, vi, mul2(cBr, vis))));
    }
}

// specialization: input state purely real (si == 0)
__device__ __forceinline__ void rot_q0_real(ull* sr, ull* si, const ull* rec) {
    ull cAr = __ldg(rec + 0), cBr = __ldg(rec + 1);
    ull cAi = __ldg(rec + 2), cBi = __ldg(rec + 3);
#pragma unroll
    for (int k = 0; k < 8; k++) {
        ull vr = sr[k];
        ull vrs = swap2(vr);
        sr[k] = fma2(cAr, vr, mul2(cBr, vrs));
        si[k] = fma2(cAi, vr, mul2(cBi, vrs));
    }
}

template <int P>
__device__ __forceinline__ void rot_local(ull* sr, ull* si, const ull* rec) {
    ull s00r = __ldg(rec + 0), s00i = __ldg(rec + 1), n00i = __ldg(rec + 2);
    ull s01r = __ldg(rec + 3), s01i = __ldg(rec + 4), n01i = __ldg(rec + 5);
    ull s10r = __ldg(rec + 6), s10i = __ldg(rec + 7), n10i = __ldg(rec + 8);
    ull s11r = __ldg(rec + 9), s11i = __ldg(rec + 10), n11i = __ldg(rec + 11);
#pragma unroll
    for (int t = 0; t < 4; t++) {
        const int k0 = ((t >> P) << (P + 1)) | (t & ((1 << P) - 1));
        const int k1 = k0 | (1 << P);
        ull ar = sr[k0], ai = si[k0], br = sr[k1], bi = si[k1];
        sr[k0] = fma2(s00r, ar, fma2(n00i, ai, fma2(s01r, br, mul2(n01i, bi))));
        si[k0] = fma2(s00r, ai, fma2(s00i, ar, fma2(s01r, bi, mul2(s01i, br))));
        sr[k1] = fma2(s10r, ar, fma2(n10i, ai, fma2(s11r, br, mul2(n11i, bi))));
        si[k1] = fma2(s10r, ai, fma2(s10i, ar, fma2(s11r, bi, mul2(s11i, br))));
    }
}

__device__ __forceinline__ void rot_cross(ull* sr, ull* si, const ull* rec, int m, bool hi) {
    ull var_ = hi ? __ldg(rec + 1) : __ldg(rec + 0);
    ull vai_ = hi ? __ldg(rec + 3) : __ldg(rec + 2);
    ull nvai = hi ? __ldg(rec + 5) : __ldg(rec + 4);
    ull vbr_ = hi ? __ldg(rec + 7) : __ldg(rec + 6);
    ull vbi_ = hi ? __ldg(rec + 9) : __ldg(rec + 8);
    ull nvbi = hi ? __ldg(rec + 11) : __ldg(rec + 10);
#pragma unroll
    for (int k = 0; k < 8; k++) {
        ull pr = __shfl_xor_sync(FULL, sr[k], m);
        ull pi = __shfl_xor_sync(FULL, si[k], m);
        ull mr = sr[k], mi = si[k];
        sr[k] = fma2(var_, mr, fma2(nvai, mi, fma2(vbr_, pr, mul2(nvbi, pi))));
        si[k] = fma2(var_, mi, fma2(vai_, mr, fma2(vbr_, pi, mul2(vbi_, pr))));
    }
}

// exchange hi halves of two packs (CNOTs with control = amp bit0)
__device__ __forceinline__ void hi_swap(ull& a, ull& b) {
    float alo, ahi, blo, bhi;
    unpack2(a, alo, ahi); unpack2(b, blo, bhi);
    a = pack2(alo, bhi);  b = pack2(blo, ahi);
}

__global__ void __launch_bounds__(256) qk_main(const float* __restrict__ x,
                                               float* __restrict__ out, int n_patch) {
    const int warp = (blockIdx.x * blockDim.x + threadIdx.x) >> 5;
    const int lane = threadIdx.x & 31;
    if (warp >= n_patch) return;

    const int b = warp >> 12;
    const int h = (warp >> 6) & 63;
    const int w = warp & 63;

    float ang = 0.0f;
    if (lane < 9) {
        const int kh = lane / 3, kw = lane % 3;
        const int hh = h - 1 + kh, ww = w - 1 + kw;
        if (hh >= 0 && hh < 64 && ww >= 0 && ww < 64)
            ang = x[(b << 12) + (hh << 6) + ww];
    }

    // lane-bit parities (logical lane-qubit values after layer-0 frame update;
    // M rows = {1,3,7,15,31}: prefix parities of physical lane bits)
    const int b0 = lane & 1, b1 = (lane >> 1) & 1, b2 = (lane >> 2) & 1;
    const int b3 = (lane >> 3) & 1, b4 = (lane >> 4) & 1;
    const int q4h = b0, q5h = q4h ^ b1, q6h = q5h ^ b2, q7h = q6h ^ b3, q8h = q7h ^ b4;

    // ---- AngleEmbedding as direct product-state construction (zero shuffles
    //      beyond the 9 angle broadcasts). Phase (-i)^{|x|} is folded into the
    //      layer-0 Rot records, so the constructed state is purely REAL. ----
    float cq[NQ], sq[NQ];
#pragma unroll
    for (int q = 0; q < NQ; q++) {
        float a = __shfl_sync(FULL, ang, q);
        __sincosf(0.5f * a, &sq[q], &cq[q]);
    }
    // lane factor over qubits 4..8 (amp index bit q = qubit value; lane bits = qubits 4..8)
    float L = (b0 ? sq[4] : cq[4]);
    L *= (b1 ? sq[5] : cq[5]);
    L *= (b2 ? sq[6] : cq[6]);
    L *= (b3 ? sq[7] : cq[7]);
    L *= (b4 ? sq[8] : cq[8]);
    // tensor tree over qubits 1..3 (pack-index bits 0..2)
    const float a0 = cq[1] * L, a1 = sq[1] * L;
    const float t0 = a0 * cq[2], t1 = a1 * cq[2], t2 = a0 * sq[2], t3 = a1 * sq[2];
    const ull u0 = pack2(cq[0], sq[0]);  // qubit 0 = pack lo/hi

    ull sr[8], si[8];
    sr[0] = mul2(u0, splat2(t0 * cq[3]));
    sr[1] = mul2(u0, splat2(t1 * cq[3]));
    sr[2] = mul2(u0, splat2(t2 * cq[3]));
    sr[3] = mul2(u0, splat2(t3 * cq[3]));
    sr[4] = mul2(u0, splat2(t0 * sq[3]));
    sr[5] = mul2(u0, splat2(t1 * sq[3]));
    sr[6] = mul2(u0, splat2(t2 * sq[3]));
    sr[7] = mul2(u0, splat2(t3 * sq[3]));
#pragma unroll
    for (int k = 0; k < 8; k++) si[k] = 0ull;

#define REC(L_, Q_) (&g_rec[((L_) * NQ + (Q_)) * 12])

    // ---- Layer 0 rots (frame M = I: masks 1,2,4,8,16; hi = lane bit) ----
    rot_q0_real(sr, si, REC(0, 0));  // real-input specialization
    rot_local<0>(sr, si, REC(0, 1));
    rot_local<1>(sr, si, REC(0, 2));
    rot_local<2>(sr, si, REC(0, 3));
    rot_cross(sr, si, REC(0, 4), 1, b0);
    rot_cross(sr, si, REC(0, 5), 2, b1);
    rot_cross(sr, si, REC(0, 6), 4, b2);
    rot_cross(sr, si, REC(0, 7), 8, b3);
    rot_cross(sr, si, REC(0, 8), 16, b4);

    // ---- Layer 0 CNOT ring r=1 ----
    // (0,1): hi-half exchange between pack pairs (k, k+1)
    hi_swap(sr[0], sr[1]); hi_swap(sr[2], sr[3]); hi_swap(sr[4], sr[5]); hi_swap(sr[6], sr[7]);
    hi_swap(si[0], si[1]); hi_swap(si[2], si[3]); hi_swap(si[4], si[5]); hi_swap(si[6], si[7]);
    // (1,2): pack swaps 1<->3, 5<->7
    { ull t; t = sr[1]; sr[1] = sr[3]; sr[3] = t; t = sr[5]; sr[5] = sr[7]; sr[7] = t;
            t = si[1]; si[1] = si[3]; si[3] = t; t = si[5]; si[5] = si[7]; si[7] = t; }
    // (2,3): pack swaps 2<->6, 3<->7
    { ull t; t = sr[2]; sr[2] = sr[6]; sr[6] = t; t = sr[3]; sr[3] = sr[7]; sr[7] = t;
            t = si[2]; si[2] = si[6]; si[6] = t; t = si[3]; si[3] = si[7]; si[7] = t; }
    // (3,4): control amp bit3 (packs 4..7), target qubit4 -> shfl mask 1 (M = I here)
#pragma unroll
    for (int k = 4; k < 8; k++) {
        sr[k] = __shfl_xor_sync(FULL, sr[k], 1);
        si[k] = __shfl_xor_sync(FULL, si[k], 1);
    }
    // (4,5),(5,6),(6,7),(7,8): absorbed into lane-frame M (rows -> {1,3,7,15,31})
    // (8,0): folded into Rot(1,0) below (control = logical q8 = parity(lane&31) = q8h)

    // ---- Layer 1 rots (frame M = {1,3,7,15,31}: masks {3,6,12,24,16}, hi = prefix parities) ----
    rot_q0(sr, si, REC(1, 0), q8h != 0);  // includes folded CNOT(8,0)
    rot_local<0>(sr, si, REC(1, 1));
    rot_local<1>(sr, si, REC(1, 2));
    rot_local<2>(sr, si, REC(1, 3));
    rot_cross(sr, si, REC(1, 4), 3, q4h);
    rot_cross(sr, si, REC(1, 5), 6, q5h);
    rot_cross(sr, si, REC(1, 6), 12, q6h);
    rot_cross(sr, si, REC(1, 7), 24, q7h);
    rot_cross(sr, si, REC(1, 8), 16, q8h);

    // ---- Layer 1 CNOT ring r=2 ----
    // (0,2): hi-half exchange pairs (k, k^2), k in {0,1,4,5}
    hi_swap(sr[0], sr[2]); hi_swap(sr[1], sr[3]); hi_swap(sr[4], sr[6]); hi_swap(sr[5], sr[7]);
    hi_swap(si[0], si[2]); hi_swap(si[1], si[3]); hi_swap(si[4], si[6]); hi_swap(si[5], si[7]);
    // (1,3): pack swaps 1<->5, 3<->7
    { ull t; t = sr[1]; sr[1] = sr[5]; sr[5] = t; t = sr[3]; sr[3] = sr[7]; sr[7] = t;
            t = si[1]; si[1] = si[5]; si[5] = t; t = si[3]; si[3] = si[7]; si[7] = t; }
    // (2,4): control amp bit2 (packs 2,3,6,7), target q4 -> mask M^-1 e0 = 3
    sr[2] = __shfl_xor_sync(FULL, sr[2], 3); si[2] = __shfl_xor_sync(FULL, si[2], 3);
    sr[3] = __shfl_xor_sync(FULL, sr[3], 3); si[3] = __shfl_xor_sync(FULL, si[3], 3);
    sr[6] = __shfl_xor_sync(FULL, sr[6], 3); si[6] = __shfl_xor_sync(FULL, si[6], 3);
    sr[7] = __shfl_xor_sync(FULL, sr[7], 3); si[7] = __shfl_xor_sync(FULL, si[7], 3);
    // (3,5): control amp bit3 (packs 4..7), target q5 -> mask M^-1 e1 = 6
#pragma unroll
    for (int k = 4; k < 8; k++) {
        sr[k] = __shfl_xor_sync(FULL, sr[k], 6);
        si[k] = __shfl_xor_sync(FULL, si[k], 6);
    }
    // (4,6),(5,7),(6,8): absorbed into frame M (rows -> {1,3,6,12,25})
    // (7,0): folded into measurement sign (cond = parity(lane & 12) = b2^b3)
    // (8,1): permutes amps within fixed bit0 -> no effect on <Z_0>, dropped

    // ---- <Z_0>: sign by amp bit0 = pack lo(+)/hi(-) ----
    float z = 0.0f;
#pragma unroll
    for (int k = 0; k < 8; k++) {
        ull pw = fma2(sr[k], sr[k], mul2(si[k], si[k]));
        float plo, phi; unpack2(pw, plo, phi);
        z += plo - phi;
    }
    if (b2 ^ b3) z = -z;  // folded CNOT(7,0)
#pragma unroll
    for (int o = 16; o > 0; o >>= 1) z += __shfl_xor_sync(FULL, z, o);

    if (lane == 0) out[warp] = z;
#undef REC
}

extern "C" void kernel_launch(void* const* d_in, const int* in_sizes, int n_in,
                              void* d_out, int out_size) {
    const float* x;
    const float* wts;
    if (n_in >= 2 && in_sizes[0] == NL * NQ * 3) {
        wts = (const float*)d_in[0];
        x = (const float*)d_in[1];
    } else {
        x = (const float*)d_in[0];
        wts = (const float*)d_in[1];
    }

    rot_precompute<<<1, 32>>>(wts);

    const int n_patch = out_size;          // 32768
    const int warps_per_block = 256 / 32;  // 8
    const int blocks = (n_patch + warps_per_block - 1) / warps_per_block;
    qk_main<<<blocks, 256>>>(x, (float*)d_out, n_patch);
}

// round 12
// speedup vs baseline: 3.5185x; 2.6350x over previous
#include <cuda_runtime.h>

#define FULL 0xFFFFFFFFu
#define NQ 9
#define NL 2

using ull = unsigned long long;

// ---------- f32x2 helpers (FFMA2 via PTX; ptxas won't auto-fuse) ----------
__device__ __forceinline__ ull fma2(ull a, ull b, ull c) {
    ull d; asm("fma.rn.f32x2 %0, %1, %2, %3;" : "=l"(d) : "l"(a), "l"(b), "l"(c)); return d;
}
__device__ __forceinline__ ull mul2(ull a, ull b) {
    ull d; asm("mul.rn.f32x2 %0, %1, %2;" : "=l"(d) : "l"(a), "l"(b)); return d;
}
__device__ __forceinline__ ull pack2(float lo, float hi) {
    ull d; asm("mov.b64 %0, {%1, %2};" : "=l"(d) : "f"(lo), "f"(hi)); return d;
}
__device__ __forceinline__ void unpack2(ull v, float& lo, float& hi) {
    asm("mov.b64 {%0, %1}, %2;" : "=f"(lo), "=f"(hi) : "l"(v));
}
__device__ __forceinline__ ull swap2(ull v) { float lo, hi; unpack2(v, lo, hi); return pack2(hi, lo); }
__device__ __forceinline__ ull splat2(float x) { return pack2(x, x); }

// ---------- precomputed tables ----------
// g_v: per qubit q (layer-0 Rot folded with RX action on |0>):
//   [u00r,u00i,u10r,u10i, m01r,m01i,m11r,m11i]  where m = -i*u (column 1)
//   v(b) = u_col0(b)*cos + m_col1(b)*sin   (cos,sin real -> linear)
__device__ float g_v[NQ * 8];
// g_A: 5 records x 5 ull for A_q = Rot(1,q)^† Z Rot(1,q), q in {0,1,3,5,7}
//   A = [[a, b],[conj(b), -a]], a real, b = br + i*bi
//   rec 0 (A0, in-pack form): [pack(a,-a), pack(-a,a), splat(br), pack(-bi,bi), pack(bi,-bi)]
//   recs 1..4 (A1,A3,A5,A7): [splat(a), splat(-a), splat(br), splat(bi), splat(-bi)]
__device__ ull g_A[25];

__global__ void precompute(const float* __restrict__ w) {
    int i = threadIdx.x;
    if (i < NQ) {
        float phi = w[i * 3 + 0], theta = w[i * 3 + 1], omega = w[i * 3 + 2];
        float st, ct; sincosf(0.5f * theta, &st, &ct);
        float sp, cp; sincosf(0.5f * (phi + omega), &sp, &cp);
        float sm, cm; sincosf(0.5f * (phi - omega), &sm, &cm);
        float u00r = cp * ct, u00i = -sp * ct;
        float u01r = -cm * st, u01i = -sm * st;
        float u10r = cm * st,  u10i = -sm * st;
        float u11r = cp * ct,  u11i = sp * ct;
        float* r = &g_v[i * 8];
        r[0] = u00r; r[1] = u00i; r[2] = u10r; r[3] = u10i;
        // m = -i*u: (ur + i*ui)*(-i) = ui - i*ur
        r[4] = u01i; r[5] = -u01r; r[6] = u11i; r[7] = -u11r;
    }
    if (i < 5) {
        const int ql[5] = {0, 1, 3, 5, 7};
        int j = NQ + ql[i];  // layer 1
        float phi = w[j * 3 + 0], theta = w[j * 3 + 1], omega = w[j * 3 + 2];
        float st, ct; sincosf(0.5f * theta, &st, &ct);
        float sp, cp; sincosf(0.5f * (phi + omega), &sp, &cp);
        float sm, cm; sincosf(0.5f * (phi - omega), &sm, &cm);
        float u00r = cp * ct, u00i = -sp * ct;
        float u01r = -cm * st, u01i = -sm * st;
        float u10r = cm * st,  u10i = -sm * st;
        float u11r = cp * ct,  u11i = sp * ct;
        // A = U^† Z U: a = |u00|^2 - |u10|^2 ; b = conj(u00)*u01 - conj(u10)*u11
        float a  = (u00r * u00r + u00i * u00i) - (u10r * u10r + u10i * u10i);
        float br = (u00r * u01r + u00i * u01i) - (u10r * u11r + u10i * u11i);
        float bi = (u00r * u01i - u00i * u01r) - (u10r * u11i - u10i * u11r);
        ull* r = &g_A[i * 5];
        if (i == 0) {
            r[0] = pack2(a, -a); r[1] = pack2(-a, a);
            r[2] = splat2(br);
            r[3] = pack2(-bi, bi); r[4] = pack2(bi, -bi);
        } else {
            r[0] = splat2(a); r[1] = splat2(-a);
            r[2] = splat2(br); r[3] = splat2(bi); r[4] = splat2(-bi);
        }
    }
}

// exchange hi halves of two packs (CNOTs with control = amp bit0)
__device__ __forceinline__ void hi_swap(ull& a, ull& b) {
    float alo, ahi, blo, bhi;
    unpack2(a, alo, ahi); unpack2(b, blo, bhi);
    a = pack2(alo, bhi);  b = pack2(blo, ahi);
}

__global__ void __launch_bounds__(128) qk_main(const float* __restrict__ x,
                                               float* __restrict__ out, int n_patch) {
    const int warp = (blockIdx.x * blockDim.x + threadIdx.x) >> 5;
    const int lane = threadIdx.x & 31;
    if (warp >= n_patch) return;

    const int b = warp >> 12;
    const int h = (warp >> 6) & 63;
    const int w = warp & 63;

    float ang = 0.0f;
    if (lane < 9) {
        const int kh = lane / 3, kw = lane % 3;
        const int hh = h - 1 + kh, ww = w - 1 + kw;
        if (hh >= 0 && hh < 64 && ww >= 0 && ww < 64)
            ang = x[(b << 12) + (hh << 6) + ww];
    }

    const int b0 = lane & 1, b1 = (lane >> 1) & 1, b2 = (lane >> 2) & 1;
    const int b3 = (lane >> 3) & 1, b4 = (lane >> 4) & 1;
    // logical lane-qubit values after layer-0 frame absorption (prefix parities)
    const int q5h = b0 ^ b1;
    const int q7h = q5h ^ b2 ^ b3;
    const int q8h = q7h ^ b4;

    // ---- embedding ⊗ layer-0 rots: per-qubit 2-vectors v_q = Rot(0,q)·RX(a_q)|0> ----
    const float4* gv4 = reinterpret_cast<const float4*>(g_v);
    float e[4][4];            // q=0..3: {v0r, v0i, v1r, v1i}
    float Fr = 1.0f, Fi = 0.0f;  // lane factor over qubits 4..8
#pragma unroll
    for (int q = 0; q < NQ; q++) {
        float aq = __shfl_sync(FULL, ang, q);
        float s_, c_; __sincosf(0.5f * aq, &s_, &c_);
        float4 A = __ldg(&gv4[q * 2]);
        float4 B = __ldg(&gv4[q * 2 + 1]);
        float w0r = A.x * c_ + B.x * s_;
        float w0i = A.y * c_ + B.y * s_;
        float w1r = A.z * c_ + B.z * s_;
        float w1i = A.w * c_ + B.w * s_;
        if (q < 4) {
            e[q][0] = w0r; e[q][1] = w0i; e[q][2] = w1r; e[q][3] = w1i;
        } else {
            const int bit = (lane >> (q - 4)) & 1;
            float vr = bit ? w1r : w0r, vi = bit ? w1i : w0i;
            float nFr = Fr * vr - Fi * vi;
            Fi = Fr * vi + Fi * vr;
            Fr = nFr;
        }
    }
    // tensor tree over pack qubits 1..3 (pack bits 0..2), F folded into q3
    float mr[4], mi[4];
#pragma unroll
    for (int j = 0; j < 4; j++) {
        const int i1 = (j & 1) ? 2 : 0, i2 = (j & 2) ? 2 : 0;
        mr[j] = e[1][i1] * e[2][i2] - e[1][i1 + 1] * e[2][i2 + 1];
        mi[j] = e[1][i1] * e[2][i2 + 1] + e[1][i1 + 1] * e[2][i2];
    }
    float wr[2], wi[2];
#pragma unroll
    for (int bq = 0; bq < 2; bq++) {
        const int i3 = bq ? 2 : 0;
        wr[bq] = Fr * e[3][i3] - Fi * e[3][i3 + 1];
        wi[bq] = Fr * e[3][i3 + 1] + Fi * e[3][i3];
    }
    const ull v0r = pack2(e[0][0], e[0][2]);  // qubit 0 = pack lo/hi
    const ull v0i = pack2(e[0][1], e[0][3]);

    ull sr[8], si[8];
#pragma unroll
    for (int k = 0; k < 8; k++) {
        const float Gr = mr[k & 3] * wr[k >> 2] - mi[k & 3] * wi[k >> 2];
        const float Gi = mr[k & 3] * wi[k >> 2] + mi[k & 3] * wr[k >> 2];
        sr[k] = fma2(splat2(Gr), v0r, mul2(splat2(-Gi), v0i));
        si[k] = fma2(splat2(Gr), v0i, mul2(splat2(Gi), v0r));
    }

    // ---- Layer 0 CNOT ring r=1 ----
    // (0,1): hi-half exchange between pack pairs (k, k^1)
    hi_swap(sr[0], sr[1]); hi_swap(sr[2], sr[3]); hi_swap(sr[4], sr[5]); hi_swap(sr[6], sr[7]);
    hi_swap(si[0], si[1]); hi_swap(si[2], si[3]); hi_swap(si[4], si[5]); hi_swap(si[6], si[7]);
    // (1,2): pack swaps 1<->3, 5<->7
    { ull t; t = sr[1]; sr[1] = sr[3]; sr[3] = t; t = sr[5]; sr[5] = sr[7]; sr[7] = t;
            t = si[1]; si[1] = si[3]; si[3] = t; t = si[5]; si[5] = si[7]; si[7] = t; }
    // (2,3): pack swaps 2<->6, 3<->7
    { ull t; t = sr[2]; sr[2] = sr[6]; sr[6] = t; t = sr[3]; sr[3] = sr[7]; sr[7] = t;
            t = si[2]; si[2] = si[6]; si[6] = t; t = si[3]; si[3] = si[7]; si[7] = t; }
    // (3,4): control amp bit3 (packs 4..7), target q4 -> shfl mask 1 (frame = I)
#pragma unroll
    for (int k = 4; k < 8; k++) {
        sr[k] = __shfl_xor_sync(FULL, sr[k], 1);
        si[k] = __shfl_xor_sync(FULL, si[k], 1);
    }
    // (4,5)..(7,8): absorbed into lane frame (logical = prefix parities)
    // (8,0): folded into A0 coefficient select (q8h) below.

    // ---- Measurement: E = <A1 A3 A5 ψ | A0 A7 ψ>  (O = Z0Z1Z3Z5Z7 pulled through L1) ----
    // coefficient selects
    const ull va5 = __ldg(g_A + (q5h ? 16 : 15));
    const ull vbr5 = __ldg(g_A + 17);
    const ull vbi5 = __ldg(g_A + (q5h ? 19 : 18));
    const ull nvbi5 = __ldg(g_A + (q5h ? 18 : 19));
    const ull va7 = __ldg(g_A + (q7h ? 21 : 20));
    const ull vbr7 = __ldg(g_A + 22);
    const ull vbi7 = __ldg(g_A + (q7h ? 24 : 23));
    const ull nvbi7 = __ldg(g_A + (q7h ? 23 : 24));
    const ull cA  = __ldg(g_A + (q8h ? 1 : 0));
    const ull cBr = __ldg(g_A + 2);
    const ull cNI = __ldg(g_A + (q8h ? 4 : 3));
    const ull cPI = __ldg(g_A + (q8h ? 3 : 4));

    ull lr[8], li[8];
    // single cross pass: L0 = A5 ψ (mask 6), R = A0(A7 ψ) (mask 24 + in-pack A0)
#pragma unroll
    for (int k = 0; k < 8; k++) {
        const ull p6r = __shfl_xor_sync(FULL, sr[k], 6);
        const ull p6i = __shfl_xor_sync(FULL, si[k], 6);
        const ull p24r = __shfl_xor_sync(FULL, sr[k], 24);
        const ull p24i = __shfl_xor_sync(FULL, si[k], 24);
        lr[k] = fma2(va5, sr[k], fma2(vbr5, p6r, mul2(nvbi5, p6i)));
        li[k] = fma2(va5, si[k], fma2(vbr5, p6i, mul2(vbi5, p6r)));
        const ull tr = fma2(va7, sr[k], fma2(vbr7, p24r, mul2(nvbi7, p24i)));
        const ull ti = fma2(va7, si[k], fma2(vbr7, p24i, mul2(vbi7, p24r)));
        sr[k] = fma2(cA, tr, fma2(cBr, swap2(tr), mul2(cNI, swap2(ti))));
        si[k] = fma2(cA, ti, fma2(cBr, swap2(ti), mul2(cPI, swap2(tr))));
    }

    // A1 on L (pack bit0 pairs)
    {
        const ull sa = __ldg(g_A + 5), sna = __ldg(g_A + 6);
        const ull sbr = __ldg(g_A + 7), sbi = __ldg(g_A + 8), snbi = __ldg(g_A + 9);
#pragma unroll
        for (int t = 0; t < 4; t++) {
            const int k0 = t * 2, k1 = k0 + 1;
            const ull Lr = lr[k0], Li = li[k0], Hr = lr[k1], Hi = li[k1];
            lr[k0] = fma2(sa, Lr, fma2(sbr, Hr, mul2(snbi, Hi)));
            li[k0] = fma2(sa, Li, fma2(sbr, Hi, mul2(sbi, Hr)));
            lr[k1] = fma2(sna, Hr, fma2(sbr, Lr, mul2(sbi, Li)));
            li[k1] = fma2(sna, Hi, fma2(sbr, Li, mul2(snbi, Lr)));
        }
    }
    // A3 on L (pack bit2 pairs)
    {
        const ull sa = __ldg(g_A + 10), sna = __ldg(g_A + 11);
        const ull sbr = __ldg(g_A + 12), sbi = __ldg(g_A + 13), snbi = __ldg(g_A + 14);
#pragma unroll
        for (int t = 0; t < 4; t++) {
            const int k0 = t, k1 = t + 4;
            const ull Lr = lr[k0], Li = li[k0], Hr = lr[k1], Hi = li[k1];
            lr[k0] = fma2(sa, Lr, fma2(sbr, Hr, mul2(snbi, Hi)));
            li[k0] = fma2(sa, Li, fma2(sbr, Hi, mul2(sbi, Hr)));
            lr[k1] = fma2(sna, Hr, fma2(sbr, Lr, mul2(sbi, Li)));
            li[k1] = fma2(sna, Hi, fma2(sbr, Li, mul2(snbi, Lr)));
        }
    }

    // E = Σ Re(conj(L)·R) = Σ (Lr·Rr + Li·Ri)
    ull acc = 0ull;
#pragma unroll
    for (int k = 0; k < 8; k++)
        acc = fma2(lr[k], sr[k], fma2(li[k], si[k], acc));
    float zlo, zhi; unpack2(acc, zlo, zhi);
    float z = zlo + zhi;
#pragma unroll
    for (int o = 16; o > 0; o >>= 1) z += __shfl_xor_sync(FULL, z, o);

    if (lane == 0) out[warp] = z;
}

extern "C" void kernel_launch(void* const* d_in, const int* in_sizes, int n_in,
                              void* d_out, int out_size) {
    const float* x;
    const float* wts;
    if (n_in >= 2 && in_sizes[0] == NL * NQ * 3) {
        wts = (const float*)d_in[0];
        x = (const float*)d_in[1];
    } else {
        x = (const float*)d_in[0];
        wts = (const float*)d_in[1];
    }

    precompute<<<1, 32>>>(wts);

    const int n_patch = out_size;          // 32768
    const int warps_per_block = 128 / 32;  // 4
    const int blocks = (n_patch + warps_per_block - 1) / warps_per_block;
    qk_main<<<blocks, 128>>>(x, (float*)d_out, n_patch);
}

// round 13
// speedup vs baseline: 14.9508x; 4.2492x over previous
#include <cuda_runtime.h>

#define NQ 9

// ---------- complex helpers ----------
struct C { float r, i; };
__device__ __forceinline__ C cmul(C a, C b)  { return {a.r * b.r - a.i * b.i, a.r * b.i + a.i * b.r}; }
__device__ __forceinline__ C cmulj(C a, C b) { return {a.r * b.r + a.i * b.i, a.i * b.r - a.r * b.i}; }  // a*conj(b)
__device__ __forceinline__ C cadd(C a, C b)  { return {a.r + b.r, a.i + b.i}; }
__device__ __forceinline__ C cscale(C a, float s) { return {a.r * s, a.i * s}; }

// ---------- precomputed tables ----------
// g_v per qubit q: [u00r,u00i,u10r,u10i, m01r,m01i,m11r,m11i], m = -i*u_col1 of Rot(0,q).
// v_q(b) = u_col0(b)*cos(a/2) + m(b)*sin(a/2)   (v_q = Rot(0,q)·RX(a_q)|0>)
__device__ __align__(16) float g_v[NQ * 8];
// A_q = Rot(1,q)^† Z Rot(1,q) = [[a, b],[conj(b), -a]] for q in {0,1,3,5,7}
__device__ float  g_Aa[5];
__device__ float2 g_Ab[5];

__global__ void precompute(const float* __restrict__ w) {
    int i = threadIdx.x;
    if (i < NQ) {
        float phi = w[i * 3 + 0], theta = w[i * 3 + 1], omega = w[i * 3 + 2];
        float st, ct; sincosf(0.5f * theta, &st, &ct);
        float sp, cp; sincosf(0.5f * (phi + omega), &sp, &cp);
        float sm, cm; sincosf(0.5f * (phi - omega), &sm, &cm);
        float u00r = cp * ct, u00i = -sp * ct;
        float u01r = -cm * st, u01i = -sm * st;
        float u10r = cm * st,  u10i = -sm * st;
        float u11r = cp * ct,  u11i = sp * ct;
        float* r = &g_v[i * 8];
        r[0] = u00r; r[1] = u00i; r[2] = u10r; r[3] = u10i;
        // m = -i*u: (ur + i*ui)*(-i) = ui - i*ur
        r[4] = u01i; r[5] = -u01r; r[6] = u11i; r[7] = -u11r;
    }
    if (i < 5) {
        const int ql[5] = {0, 1, 3, 5, 7};
        int j = NQ + ql[i];  // layer-1 weights
        float phi = w[j * 3 + 0], theta = w[j * 3 + 1], omega = w[j * 3 + 2];
        float st, ct; sincosf(0.5f * theta, &st, &ct);
        float sp, cp; sincosf(0.5f * (phi + omega), &sp, &cp);
        float sm, cm; sincosf(0.5f * (phi - omega), &sm, &cm);
        float u00r = cp * ct, u00i = -sp * ct;
        float u01r = -cm * st, u01i = -sm * st;
        float u10r = cm * st,  u10i = -sm * st;
        float u11r = cp * ct,  u11i = sp * ct;
        // A(r,c) = conj(u0r)u0c - conj(u1r)u1c
        g_Aa[i] = (u00r * u00r + u00i * u00i) - (u10r * u10r + u10i * u10i);
        g_Ab[i] = make_float2((u00r * u01r + u00i * u01i) - (u10r * u11r + u10i * u11i),
                              (u00r * u01i - u00i * u01r) - (u10r * u11i - u10i * u11r));
    }
}

// A(z', z) scaling: (0,0)->a, (1,1)->-a, (0,1)->b, (1,0)->conj(b). r,c compile-time.
__device__ __forceinline__ C ascale(int r, int c, C X, float a, C b) {
    if (r == 0 && c == 0) return cscale(X, a);
    if (r == 1 && c == 1) return cscale(X, -a);
    if (r == 0 && c == 1) return cmul(X, b);
    return cmulj(X, b);
}

// delta-site (A = I): y[z] = sum_{b,b'} v(z^b) conj(v(z^b')) X[b][b']
__device__ __forceinline__ void collapse(const C vq[2], const C X[2][2], C y[2]) {
#pragma unroll
    for (int z = 0; z < 2; z++) {
        C R0 = cadd(cmulj(X[0][0], vq[z]), cmulj(X[0][1], vq[z ^ 1]));
        C R1 = cadd(cmulj(X[1][0], vq[z]), cmulj(X[1][1], vq[z ^ 1]));
        y[z] = cadd(cmul(vq[z], R0), cmul(vq[z ^ 1], R1));
    }
}

// S-site (shared bond-in): X[z][z'] = A(z',z) * sum_b v(z^b) conj(v(z'^b)) y[b]
__device__ __forceinline__ void expand(const C vq[2], C X[2][2], const C y[2], float a, C b) {
    C t00 = cmul(vq[0], y[0]), t01 = cmul(vq[1], y[1]);  // t[z=0][b]
    C t10 = cmul(vq[1], y[0]), t11 = cmul(vq[0], y[1]);  // t[z=1][b]
#pragma unroll
    for (int zp = 0; zp < 2; zp++) {
        C e0 = cadd(cmulj(t00, vq[zp]), cmulj(t01, vq[zp ^ 1]));  // z=0
        C e1 = cadd(cmulj(t10, vq[zp]), cmulj(t11, vq[zp ^ 1]));  // z=1
        X[0][zp] = ascale(zp, 0, e0, a, b);
        X[1][zp] = ascale(zp, 1, e1, a, b);
    }
}

// E = <psi| A0 A1 A3 A5 A7 |psi>, psi = CNOTring(r=1) (⊗ v_q):
//   psi(z) = prod_q v_q(y_q), y_q = z_q^z_{q-1} (q>=2), y_1 = z_1^y_0, y_0 = z_0^z_8.
// Operator is delta on qubits {2,4,6,8} => bra/ket bond collapses to dim 2 there,
// including the wrap bond (z'_8 = z_8 = w8): ring trace = sum over 2 wrap values.
__global__ void __launch_bounds__(128) qk_main(const float* __restrict__ x,
                                               float* __restrict__ out, int n_patch) {
    const int p = blockIdx.x * blockDim.x + threadIdx.x;
    if (p >= n_patch) return;
    const int bb = p >> 12, h = (p >> 6) & 63, w = p & 63;

    // per-qubit local vectors v_q (embedding angle folded with layer-0 Rot)
    C v[NQ][2];
    const float4* gv4 = reinterpret_cast<const float4*>(g_v);
#pragma unroll
    for (int q = 0; q < NQ; q++) {
        const int kh = q / 3, kw = q % 3;
        const int hh = h - 1 + kh, ww = w - 1 + kw;
        float a = 0.0f;
        if (hh >= 0 && hh < 64 && ww >= 0 && ww < 64)
            a = __ldg(&x[(bb << 12) + (hh << 6) + ww]);
        float s_, c_; __sincosf(0.5f * a, &s_, &c_);
        float4 A = __ldg(&gv4[2 * q]);
        float4 B = __ldg(&gv4[2 * q + 1]);
        v[q][0] = {A.x * c_ + B.x * s_, A.y * c_ + B.y * s_};
        v[q][1] = {A.z * c_ + B.z * s_, A.w * c_ + B.w * s_};
    }

    float Aa[5]; C Ab[5];
#pragma unroll
    for (int i = 0; i < 5; i++) {
        Aa[i] = __ldg(&g_Aa[i]);
        float2 t = __ldg(&g_Ab[i]);
        Ab[i] = {t.x, t.y};
    }

    float E = 0.0f;
#pragma unroll
    for (int w8 = 0; w8 < 2; w8++) {
        // site 0 (wrap): s[u][u'] = A0(u'^w8, u^w8) v0(u) conj(v0(u')),  u = y_0
        C s[2][2];
#pragma unroll
        for (int u = 0; u < 2; u++)
#pragma unroll
            for (int up = 0; up < 2; up++)
                s[u][up] = ascale(up ^ w8, u ^ w8, cmulj(v[0][u], v[0][up]), Aa[0], Ab[0]);

        // site 1 (4->4): X[z][z'] = A1(z',z) sum_{u,u'} v1(z^u) conj(v1(z'^u')) s[u][u']
        C X[2][2];
        {
            C W[2][2];
#pragma unroll
            for (int z = 0; z < 2; z++)
#pragma unroll
                for (int up = 0; up < 2; up++)
                    W[z][up] = cadd(cmul(v[1][z], s[0][up]), cmul(v[1][z ^ 1], s[1][up]));
#pragma unroll
            for (int z = 0; z < 2; z++)
#pragma unroll
                for (int zp = 0; zp < 2; zp++) {
                    C t = cadd(cmulj(W[z][0], v[1][zp]), cmulj(W[z][1], v[1][zp ^ 1]));
                    X[z][zp] = ascale(zp, z, t, Aa[1], Ab[1]);
                }
        }

        // alternate delta-collapse / A-expand along the chain
        C y[2];
        collapse(v[2], X, y);
        expand(v[3], X, y, Aa[2], Ab[2]);
        collapse(v[4], X, y);
        expand(v[5], X, y, Aa[3], Ab[3]);
        collapse(v[6], X, y);
        expand(v[7], X, y, Aa[4], Ab[4]);

        // site 8 closes the ring at wrap value w8:
        // E_w = sum_{z7,z7'} v8(w8^z7) conj(v8(w8^z7')) X[z7][z7']
        C r0 = cadd(cmulj(X[0][0], v[8][w8]), cmulj(X[0][1], v[8][w8 ^ 1]));
        C r1 = cadd(cmulj(X[1][0], v[8][w8]), cmulj(X[1][1], v[8][w8 ^ 1]));
        C Ew = cadd(cmul(v[8][w8], r0), cmul(v[8][w8 ^ 1], r1));
        E += Ew.r;  // E is real; imaginary parts cancel analytically
    }

    out[p] = E;
}

extern "C" void kernel_launch(void* const* d_in, const int* in_sizes, int n_in,
                              void* d_out, int out_size) {
    const float* x;
    const float* wts;
    if (n_in >= 2 && in_sizes[0] == 2 * NQ * 3) {
        wts = (const float*)d_in[0];
        x = (const float*)d_in[1];
    } else {
        x = (const float*)d_in[0];
        wts = (const float*)d_in[1];
    }

    precompute<<<1, 32>>>(wts);

    const int n_patch = out_size;  // 32768
    const int threads = 128;
    const int blocks = (n_patch + threads - 1) / threads;
    qk_main<<<blocks, threads>>>(x, (float*)d_out, n_patch);
}

// round 14
// speedup vs baseline: 16.2857x; 1.0893x over previous
#include <cuda_runtime.h>

#define NQ 9
#define FULL 0xFFFFFFFFu

// ---------- complex helpers ----------
struct C { float r, i; };
__device__ __forceinline__ C cmul(C a, C b)  { return {a.r * b.r - a.i * b.i, a.r * b.i + a.i * b.r}; }
__device__ __forceinline__ C cmulj(C a, C b) { return {a.r * b.r + a.i * b.i, a.i * b.r - a.r * b.i}; }  // a*conj(b)
__device__ __forceinline__ C cadd(C a, C b)  { return {a.r + b.r, a.i + b.i}; }
__device__ __forceinline__ C cscale(C a, float s) { return {a.r * s, a.i * s}; }

// A(z', z) scaling: (0,0)->a, (1,1)->-a, (0,1)->b, (1,0)->conj(b). r,c compile-time.
__device__ __forceinline__ C ascale(int r, int c, C X, float a, C b) {
    if (r == 0 && c == 0) return cscale(X, a);
    if (r == 1 && c == 1) return cscale(X, -a);
    if (r == 0 && c == 1) return cmul(X, b);
    return cmulj(X, b);
}

// delta-site (A = I): y[z] = sum_{b,b'} v(z^b) conj(v(z^b')) X[b][b']
__device__ __forceinline__ void collapse(const C vq[2], const C X[2][2], C y[2]) {
#pragma unroll
    for (int z = 0; z < 2; z++) {
        C R0 = cadd(cmulj(X[0][0], vq[z]), cmulj(X[0][1], vq[z ^ 1]));
        C R1 = cadd(cmulj(X[1][0], vq[z]), cmulj(X[1][1], vq[z ^ 1]));
        y[z] = cadd(cmul(vq[z], R0), cmul(vq[z ^ 1], R1));
    }
}

// S-site (shared bond-in): X[z][z'] = A(z',z) * sum_b v(z^b) conj(v(z'^b)) y[b]
__device__ __forceinline__ void expand(const C vq[2], C X[2][2], const C y[2], float a, C b) {
    C t00 = cmul(vq[0], y[0]), t01 = cmul(vq[1], y[1]);  // t[z=0][b]
    C t10 = cmul(vq[1], y[0]), t11 = cmul(vq[0], y[1]);  // t[z=1][b]
#pragma unroll
    for (int zp = 0; zp < 2; zp++) {
        C e0 = cadd(cmulj(t00, vq[zp]), cmulj(t01, vq[zp ^ 1]));  // z=0
        C e1 = cadd(cmulj(t10, vq[zp]), cmulj(t11, vq[zp ^ 1]));  // z=1
        X[0][zp] = ascale(zp, 0, e0, a, b);
        X[1][zp] = ascale(zp, 1, e1, a, b);
    }
}

// E = <psi| A0 A1 A3 A5 A7 |psi>, psi = CNOTring(r=1) (⊗ v_q):
//   psi(z) = prod_q v_q(y_q), y_q = z_q^z_{q-1} (q>=2), y_1 = z_1^y_0, y_0 = z_0^z_8.
// Operator is delta on qubits {2,4,6,8} => bra/ket bond collapses to dim 2 there,
// including the wrap bond (z'_8 = z_8 = w8). The two wrap terms (w8 = 0,1) are
// independent: each of the 2 threads per patch computes one, combined by shfl.
// Tables (layer-0 v coefficients, layer-1 A operators) are rebuilt per block in
// shared memory — no separate precompute launch.
__global__ void __launch_bounds__(128) qk_main(const float* __restrict__ x,
                                               const float* __restrict__ wts,
                                               float* __restrict__ out, int n_patch) {
    // smem tables
    __shared__ float4 sv[NQ * 2];  // per qubit: {u00r,u00i,u10r,u10i},{m01r,m01i,m11r,m11i}
    __shared__ float  sAa[5];
    __shared__ float2 sAb[5];

    const int t = threadIdx.x;
    if (t < NQ) {
        float phi = wts[t * 3 + 0], theta = wts[t * 3 + 1], omega = wts[t * 3 + 2];
        float st, ct; sincosf(0.5f * theta, &st, &ct);
        float sp, cp; sincosf(0.5f * (phi + omega), &sp, &cp);
        float sm, cm; sincosf(0.5f * (phi - omega), &sm, &cm);
        float u00r = cp * ct, u00i = -sp * ct;
        float u01r = -cm * st, u01i = -sm * st;
        float u10r = cm * st,  u10i = -sm * st;
        float u11r = cp * ct,  u11i = sp * ct;
        sv[t * 2]     = make_float4(u00r, u00i, u10r, u10i);
        // m = -i*u_col1: (ur + i*ui)*(-i) = ui - i*ur
        sv[t * 2 + 1] = make_float4(u01i, -u01r, u11i, -u11r);
    }
    if (t < 5) {
        const int ql[5] = {0, 1, 3, 5, 7};
        const int j = NQ + ql[t];  // layer-1 weights
        float phi = wts[j * 3 + 0], theta = wts[j * 3 + 1], omega = wts[j * 3 + 2];
        float st, ct; sincosf(0.5f * theta, &st, &ct);
        float sp, cp; sincosf(0.5f * (phi + omega), &sp, &cp);
        float sm, cm; sincosf(0.5f * (phi - omega), &sm, &cm);
        float u00r = cp * ct, u00i = -sp * ct;
        float u01r = -cm * st, u01i = -sm * st;
        float u10r = cm * st,  u10i = -sm * st;
        float u11r = cp * ct,  u11i = sp * ct;
        // A = U^† Z U: A(r,c) = conj(u0r)u0c - conj(u1r)u1c
        sAa[t] = (u00r * u00r + u00i * u00i) - (u10r * u10r + u10i * u10i);
        sAb[t] = make_float2((u00r * u01r + u00i * u01i) - (u10r * u11r + u10i * u11i),
                             (u00r * u01i - u00i * u01r) - (u10r * u11i - u10i * u11r));
    }
    __syncthreads();

    const int gtid = blockIdx.x * blockDim.x + t;
    const int p = gtid >> 1;          // patch
    const int w8 = gtid & 1;          // wrap-bond value handled by this thread
    if (p >= n_patch) return;
    const int bb = p >> 12, h = (p >> 6) & 63, w = p & 63;

    // per-qubit local vectors v_q (embedding angle folded with layer-0 Rot)
    C v[NQ][2];
#pragma unroll
    for (int q = 0; q < NQ; q++) {
        const int kh = q / 3, kw = q % 3;
        const int hh = h - 1 + kh, ww = w - 1 + kw;
        float a = 0.0f;
        if (hh >= 0 && hh < 64 && ww >= 0 && ww < 64)
            a = __ldg(&x[(bb << 12) + (hh << 6) + ww]);
        float s_, c_; __sincosf(0.5f * a, &s_, &c_);
        const float4 A = sv[2 * q];
        const float4 B = sv[2 * q + 1];
        v[q][0] = {A.x * c_ + B.x * s_, A.y * c_ + B.y * s_};
        v[q][1] = {A.z * c_ + B.z * s_, A.w * c_ + B.w * s_};
    }

    float Aa[5]; C Ab[5];
#pragma unroll
    for (int i = 0; i < 5; i++) {
        Aa[i] = sAa[i];
        Ab[i] = {sAb[i].x, sAb[i].y};
    }

    // site 0 (wrap): s[u][u'] = A0(u'^w8, u^w8) v0(u) conj(v0(u')),  u = y_0
    // w8 is runtime here (per-thread); expand the two A0 index patterns by select.
    C s[2][2];
#pragma unroll
    for (int u = 0; u < 2; u++)
#pragma unroll
        for (int up = 0; up < 2; up++) {
            const C base = cmulj(v[0][u], v[0][up]);
            const C e0 = ascale(up, u, base, Aa[0], Ab[0]);          // w8 = 0
            const C e1 = ascale(up ^ 1, u ^ 1, base, Aa[0], Ab[0]);  // w8 = 1
            s[u][up] = w8 ? e1 : e0;
        }

    // site 1 (4->4): X[z][z'] = A1(z',z) sum_{u,u'} v1(z^u) conj(v1(z'^u')) s[u][u']
    C X[2][2];
    {
        C W[2][2];
#pragma unroll
        for (int z = 0; z < 2; z++)
#pragma unroll
            for (int up = 0; up < 2; up++)
                W[z][up] = cadd(cmul(v[1][z], s[0][up]), cmul(v[1][z ^ 1], s[1][up]));
#pragma unroll
        for (int z = 0; z < 2; z++)
#pragma unroll
            for (int zp = 0; zp < 2; zp++) {
                C tt = cadd(cmulj(W[z][0], v[1][zp]), cmulj(W[z][1], v[1][zp ^ 1]));
                X[z][zp] = ascale(zp, z, tt, Aa[1], Ab[1]);
            }
    }

    // alternate delta-collapse / A-expand along the chain
    C y[2];
    collapse(v[2], X, y);
    expand(v[3], X, y, Aa[2], Ab[2]);
    collapse(v[4], X, y);
    expand(v[5], X, y, Aa[3], Ab[3]);
    collapse(v[6], X, y);
    expand(v[7], X, y, Aa[4], Ab[4]);

    // site 8 closes the ring at wrap value w8:
    // E_w = sum_{z7,z7'} v8(w8^z7) conj(v8(w8^z7')) X[z7][z7']
    const C v8a = v[8][w8], v8b = v[8][w8 ^ 1];
    C r0 = cadd(cmulj(X[0][0], v8a), cmulj(X[0][1], v8b));
    C r1 = cadd(cmulj(X[1][0], v8a), cmulj(X[1][1], v8b));
    C Ew = cadd(cmul(v8a, r0), cmul(v8b, r1));

    float E = Ew.r;  // E is real; imaginary parts cancel analytically
    E += __shfl_xor_sync(FULL, E, 1);  // combine the two wrap terms
    if (w8 == 0) out[p] = E;
}

extern "C" void kernel_launch(void* const* d_in, const int* in_sizes, int n_in,
                              void* d_out, int out_size) {
    const float* x;
    const float* wts;
    if (n_in >= 2 && in_sizes[0] == 2 * NQ * 3) {
        wts = (const float*)d_in[0];
        x = (const float*)d_in[1];
    } else {
        x = (const float*)d_in[0];
        wts = (const float*)d_in[1];
    }

    const int n_patch = out_size;           // 32768
    const int n_threads = 2 * n_patch;      // 2 threads per patch (w8 split)
    const int threads = 128;
    const int blocks = (n_threads + threads - 1) / threads;  // 512
    qk_main<<<blocks, threads>>>(x, wts, (float*)d_out, n_patch);
}

// round 15
// speedup vs baseline: 21.8182x; 1.3397x over previous
#include <cuda_runtime.h>

#define NQ 9

// ---------- complex helpers ----------
struct C { float r, i; };
__device__ __forceinline__ C cmul(C a, C b)  { return {a.r * b.r - a.i * b.i, a.r * b.i + a.i * b.r}; }
__device__ __forceinline__ C cmulj(C a, C b) { return {a.r * b.r + a.i * b.i, a.i * b.r - a.r * b.i}; }  // a*conj(b)
__device__ __forceinline__ C cadd(C a, C b)  { return {a.r + b.r, a.i + b.i}; }
__device__ __forceinline__ C cscale(C a, float s) { return {a.r * s, a.i * s}; }

// A(z', z) scaling: (0,0)->a, (1,1)->-a, (0,1)->b, (1,0)->conj(b). r,c compile-time.
__device__ __forceinline__ C ascale(int r, int c, C X, float a, C b) {
    if (r == 0 && c == 0) return cscale(X, a);
    if (r == 1 && c == 1) return cscale(X, -a);
    if (r == 0 && c == 1) return cmul(X, b);
    return cmulj(X, b);
}

// delta-site (A = I): y[z] = sum_{b,b'} v(z^b) conj(v(z^b')) X[b][b']
__device__ __forceinline__ void collapse(const C vq[2], const C X[2][2], C y[2]) {
#pragma unroll
    for (int z = 0; z < 2; z++) {
        C R0 = cadd(cmulj(X[0][0], vq[z]), cmulj(X[0][1], vq[z ^ 1]));
        C R1 = cadd(cmulj(X[1][0], vq[z]), cmulj(X[1][1], vq[z ^ 1]));
        y[z] = cadd(cmul(vq[z], R0), cmul(vq[z ^ 1], R1));
    }
}

// S-site: X[z][z'] = A(z',z) * sum_b v(z^b) conj(v(z'^b)) y[b]
__device__ __forceinline__ void expand(const C vq[2], C X[2][2], const C y[2], float a, C b) {
    C t00 = cmul(vq[0], y[0]), t01 = cmul(vq[1], y[1]);
    C t10 = cmul(vq[1], y[0]), t11 = cmul(vq[0], y[1]);
#pragma unroll
    for (int zp = 0; zp < 2; zp++) {
        C e0 = cadd(cmulj(t00, vq[zp]), cmulj(t01, vq[zp ^ 1]));
        C e1 = cadd(cmulj(t10, vq[zp]), cmulj(t11, vq[zp ^ 1]));
        X[0][zp] = ascale(zp, 0, e0, a, b);
        X[1][zp] = ascale(zp, 1, e1, a, b);
    }
}

// Forward half: sites 0..4 (v[0..4] = v_0..v_4). Output y4[z4] (bond after collapse at site 4).
template <int W8>
__device__ __forceinline__ void fwd_chain(const C v[5][2], const float* Aa, const C* Ab, C y4[2]) {
    // site 0 (wrap): s[u][u'] = A0(u'^W8, u^W8) v0(u) conj(v0(u'))
    C s[2][2];
#pragma unroll
    for (int u = 0; u < 2; u++)
#pragma unroll
        for (int up = 0; up < 2; up++)
            s[u][up] = ascale(up ^ W8, u ^ W8, cmulj(v[0][u], v[0][up]), Aa[0], Ab[0]);
    // site 1: X[z][z'] = A1(z',z) sum_{u,u'} v1(z^u) conj(v1(z'^u')) s[u][u']
    C X[2][2];
    {
        C W_[2][2];
#pragma unroll
        for (int z = 0; z < 2; z++)
#pragma unroll
            for (int up = 0; up < 2; up++)
                W_[z][up] = cadd(cmul(v[1][z], s[0][up]), cmul(v[1][z ^ 1], s[1][up]));
#pragma unroll
        for (int z = 0; z < 2; z++)
#pragma unroll
            for (int zp = 0; zp < 2; zp++)
                X[z][zp] = ascale(zp, z,
                                  cadd(cmulj(W_[z][0], v[1][zp]), cmulj(W_[z][1], v[1][zp ^ 1])),
                                  Aa[1], Ab[1]);
    }
    C y2[2];
    collapse(v[2], X, y2);
    expand(v[3], X, y2, Aa[2], Ab[2]);   // A3
    collapse(v[4], X, y4);
}

// Backward half (adjoint): sites 8..5 (v[0]=v5, v[1]=v6, v[2]=v7, v[3]=v8).
// Produces G s.t. E_w = sum_b G[b] * y4[b].
// Adjoint derivation:
//  closure:  T8[z][z'] = v8(W8^z) conj(v8(W8^z'))
//  thru expand-site q:  G[b] = sum_{z,z'} (T[z][z']*A(z',z)) v_q(z^b) conj(v_q(z'^b))
//  thru delta-site q:   T[b][b'] = sum_z G[z] v_q(z^b) conj(v_q(z^b'))
template <int W8>
__device__ __forceinline__ void bwd_chain(const C v[4][2], const float* Aa, const C* Ab, C G[2]) {
    C T[2][2];
#pragma unroll
    for (int z = 0; z < 2; z++)
#pragma unroll
        for (int zp = 0; zp < 2; zp++)
            T[z][zp] = cmulj(v[3][W8 ^ z], v[3][W8 ^ zp]);
    // back through site 7 (A7 = Aa[4])
#pragma unroll
    for (int z = 0; z < 2; z++)
#pragma unroll
        for (int zp = 0; zp < 2; zp++)
            T[z][zp] = ascale(zp, z, T[z][zp], Aa[4], Ab[4]);
    C G7[2];
#pragma unroll
    for (int bb = 0; bb < 2; bb++) {
        C in0 = cadd(cmulj(T[0][0], v[2][bb]), cmulj(T[0][1], v[2][bb ^ 1]));
        C in1 = cadd(cmulj(T[1][0], v[2][bb]), cmulj(T[1][1], v[2][bb ^ 1]));
        G7[bb] = cadd(cmul(v[2][bb], in0), cmul(v[2][bb ^ 1], in1));
    }
    // back through site 6 (delta)
    C T6[2][2];
#pragma unroll
    for (int bb = 0; bb < 2; bb++)
#pragma unroll
        for (int bp = 0; bp < 2; bp++)
            T6[bb][bp] = cadd(cmul(G7[0], cmulj(v[1][bb], v[1][bp])),
                              cmul(G7[1], cmulj(v[1][bb ^ 1], v[1][bp ^ 1])));
    // back through site 5 (A5 = Aa[3])
#pragma unroll
    for (int z = 0; z < 2; z++)
#pragma unroll
        for (int zp = 0; zp < 2; zp++)
            T6[z][zp] = ascale(zp, z, T6[z][zp], Aa[3], Ab[3]);
#pragma unroll
    for (int bb = 0; bb < 2; bb++) {
        C in0 = cadd(cmulj(T6[0][0], v[0][bb]), cmulj(T6[0][1], v[0][bb ^ 1]));
        C in1 = cadd(cmulj(T6[1][0], v[0][bb]), cmulj(T6[1][1], v[0][bb ^ 1]));
        G[bb] = cadd(cmul(v[0][bb], in0), cmul(v[0][bb ^ 1], in1));
    }
}

// Warp-uniform role split: even warps = forward (sites 0-4), odd warps = backward
// (sites 8-5) for the SAME 32 patches; exchange G via smem, one __syncthreads.
__global__ void __launch_bounds__(128) qk_main(const float* __restrict__ x,
                                               const float* __restrict__ wts,
                                               float* __restrict__ out, int n_patch) {
    __shared__ float4 sv[NQ * 2];
    __shared__ float  sAa[5];
    __shared__ float2 sAb[5];
    __shared__ float  sG[8][64];   // G per patch-slot, component-major (conflict-free)

    const int t = threadIdx.x;
    if (t < NQ) {
        float phi = wts[t * 3 + 0], theta = wts[t * 3 + 1], omega = wts[t * 3 + 2];
        float st, ct; sincosf(0.5f * theta, &st, &ct);
        float sp, cp; sincosf(0.5f * (phi + omega), &sp, &cp);
        float sm, cm; sincosf(0.5f * (phi - omega), &sm, &cm);
        sv[t * 2]     = make_float4(cp * ct, -sp * ct, cm * st, -sm * st);
        // m = -i*u_col1: (ur + i*ui)*(-i) = ui - i*ur ; u01=(-cm*st,-sm*st), u11=(cp*ct,sp*ct)
        sv[t * 2 + 1] = make_float4(-sm * st, cm * st, sp * ct, -cp * ct);
    }
    if (t < 5) {
        const int ql[5] = {0, 1, 3, 5, 7};
        const int j = NQ + ql[t];
        float phi = wts[j * 3 + 0], theta = wts[j * 3 + 1], omega = wts[j * 3 + 2];
        float st, ct; sincosf(0.5f * theta, &st, &ct);
        float sp, cp; sincosf(0.5f * (phi + omega), &sp, &cp);
        float sm, cm; sincosf(0.5f * (phi - omega), &sm, &cm);
        float u00r = cp * ct, u00i = -sp * ct;
        float u01r = -cm * st, u01i = -sm * st;
        float u10r = cm * st,  u10i = -sm * st;
        float u11r = cp * ct,  u11i = sp * ct;
        sAa[t] = (u00r * u00r + u00i * u00i) - (u10r * u10r + u10i * u10i);
        sAb[t] = make_float2((u00r * u01r + u00i * u01i) - (u10r * u11r + u10i * u11i),
                             (u00r * u01i - u00i * u01r) - (u10r * u11i - u10i * u11r));
    }
    __syncthreads();

    const int lane = t & 31;
    const int warp = t >> 5;          // 0..3
    const int pair = warp >> 1;       // 0..1
    const int role = warp & 1;        // 0 = forward, 1 = backward
    const int slot = pair * 32 + lane;
    int p = blockIdx.x * 64 + slot;
    const bool valid = p < n_patch;
    if (!valid) p = n_patch - 1;      // clamp; barrier stays uniform
    const int bb_ = p >> 12, h = (p >> 6) & 63, w = p & 63;

    float Aa[5]; C Ab[5];
#pragma unroll
    for (int i = 0; i < 5; i++) { Aa[i] = sAa[i]; Ab[i] = {sAb[i].x, sAb[i].y}; }

    C y0[2], y1[2];  // forward outputs (role 0 only)
    if (role == 0) {
        C v[5][2];
#pragma unroll
        for (int k = 0; k < 5; k++) {
            const int q = k;
            const int hh = h - 1 + q / 3, ww = w - 1 + q % 3;
            float a = 0.0f;
            if (hh >= 0 && hh < 64 && ww >= 0 && ww < 64)
                a = __ldg(&x[(bb_ << 12) + (hh << 6) + ww]);
            float s_, c_; __sincosf(0.5f * a, &s_, &c_);
            const float4 A = sv[2 * q], B = sv[2 * q + 1];
            v[k][0] = {A.x * c_ + B.x * s_, A.y * c_ + B.y * s_};
            v[k][1] = {A.z * c_ + B.z * s_, A.w * c_ + B.w * s_};
        }
        fwd_chain<0>(v, Aa, Ab, y0);
        fwd_chain<1>(v, Aa, Ab, y1);
    } else {
        C v[4][2];
#pragma unroll
        for (int k = 0; k < 4; k++) {
            const int q = 5 + k;
            const int hh = h - 1 + q / 3, ww = w - 1 + q % 3;
            float a = 0.0f;
            if (hh >= 0 && hh < 64 && ww >= 0 && ww < 64)
                a = __ldg(&x[(bb_ << 12) + (hh << 6) + ww]);
            float s_, c_; __sincosf(0.5f * a, &s_, &c_);
            const float4 A = sv[2 * q], B = sv[2 * q + 1];
            v[k][0] = {A.x * c_ + B.x * s_, A.y * c_ + B.y * s_};
            v[k][1] = {A.z * c_ + B.z * s_, A.w * c_ + B.w * s_};
        }
        C G0[2], G1[2];
        bwd_chain<0>(v, Aa, Ab, G0);
        bwd_chain<1>(v, Aa, Ab, G1);
        sG[0][slot] = G0[0].r; sG[1][slot] = G0[0].i;
        sG[2][slot] = G0[1].r; sG[3][slot] = G0[1].i;
        sG[4][slot] = G1[0].r; sG[5][slot] = G1[0].i;
        sG[6][slot] = G1[1].r; sG[7][slot] = G1[1].i;
    }

    __syncthreads();

    if (role == 0) {
        // E = Re( sum_w sum_b y_w[b] * G_w[b] )
        float E = y0[0].r * sG[0][slot] - y0[0].i * sG[1][slot]
                + y0[1].r * sG[2][slot] - y0[1].i * sG[3][slot]
                + y1[0].r * sG[4][slot] - y1[0].i * sG[5][slot]
                + y1[1].r * sG[6][slot] - y1[1].i * sG[7][slot];
        if (valid) out[p] = E;
    }
}

extern "C" void kernel_launch(void* const* d_in, const int* in_sizes, int n_in,
                              void* d_out, int out_size) {
    const float* x;
    const float* wts;
    if (n_in >= 2 && in_sizes[0] == 2 * NQ * 3) {
        wts = (const float*)d_in[0];
        x = (const float*)d_in[1];
    } else {
        x = (const float*)d_in[0];
        wts = (const float*)d_in[1];
    }

    const int n_patch = out_size;                 // 32768
    const int patches_per_block = 64;             // 2 warp-pairs x 32 patches
    const int blocks = (n_patch + patches_per_block - 1) / patches_per_block;  // 512
    qk_main<<<blocks, 128>>>(x, wts, (float*)d_out, n_patch);
}